// round 7
// baseline (speedup 1.0000x reference)
#include <cuda_runtime.h>
#include <cuda_fp16.h>
#include <cstdint>
#include <cstddef>

// ---------------- problem dims ----------------
#define BT    16384              // B*T rows
#define HD    1024               // hidden dim
#define KD    2048               // h + x contraction dim
#define NW    4096               // 4 gates * HD weight rows
#define SEQ_OUT (16384 * 1024)   // elements per output tensor

// ---------------- GEMM tiling ----------------
#define MT      128              // CTA M
#define NT      256              // CTA N = 4 gates x 64 h (gate-interleaved)
#define KT      64               // K per SMEM stage (128 B rows, SW128)
#define NKT     (KD / KT)        // 32 k-tiles
#define THREADS 256              // 8 warps: 4 (M) x 2 (N)
#define STAGES  3
#define A_TILE  (MT * 128)       // 16 KB
#define B_TILE  (NT * 128)       // 32 KB
#define STAGE_SZ (A_TILE + B_TILE)            // 48 KB
#define SMEM_TOTAL (STAGES * STAGE_SZ)        // 144 KB (epilogue reuses it)
#define EPI_PITCH 132            // floats per row in epilogue buffer

// fp16 scratch (device globals: no runtime allocation)
__device__ __half g_A[(size_t)BT * KD];   // 64 MB  cat(a,x) fp16
__device__ __half g_W[(size_t)NW * KD];   // 16 MB  [Wf;Wi;Wc;Wo] fp16

#define DINL __device__ __forceinline__
#define SW128(o) ((uint32_t)(o) ^ ((((uint32_t)(o)) >> 3) & 0x70u))

// ---------------- PTX helpers (all plain sm_80-era: compile for compute_103) ----
DINL uint32_t smem_u32(const void* p) {
    uint32_t a;
    asm("{ .reg .u64 t; cvta.to.shared.u64 t, %1; cvt.u32.u64 %0, t; }"
        : "=r"(a) : "l"(p));
    return a;
}
DINL void cpa16(uint32_t dst, const void* src) {
    asm volatile("cp.async.cg.shared.global [%0], [%1], 16;"
                 :: "r"(dst), "l"(src));
}
DINL void cp_commit() { asm volatile("cp.async.commit_group;" ::: "memory"); }
template<int N> DINL void cp_wait() {
    asm volatile("cp.async.wait_group %0;" :: "n"(N) : "memory");
}
DINL void ldmx4(uint32_t& r0, uint32_t& r1, uint32_t& r2, uint32_t& r3, uint32_t addr) {
    asm volatile("ldmatrix.sync.aligned.m8n8.x4.shared.b16 {%0,%1,%2,%3}, [%4];"
                 : "=r"(r0), "=r"(r1), "=r"(r2), "=r"(r3) : "r"(addr));
}
DINL void mma16816(float* d, const uint32_t* a, const uint32_t* b) {
    asm volatile(
        "mma.sync.aligned.m16n8k16.row.col.f32.f16.f16.f32 "
        "{%0,%1,%2,%3}, {%4,%5,%6,%7}, {%8,%9}, {%0,%1,%2,%3};"
        : "+f"(d[0]), "+f"(d[1]), "+f"(d[2]), "+f"(d[3])
        : "r"(a[0]), "r"(a[1]), "r"(a[2]), "r"(a[3]), "r"(b[0]), "r"(b[1]));
}
DINL float sigf(float v)     { return __fdividef(1.0f, 1.0f + __expf(-v)); }
DINL float tanhfast(float v) { return 1.0f - __fdividef(2.0f, 1.0f + __expf(2.0f * v)); }

// ---------------- conversion kernels ----------------
// g_A[bt, k] = fp16( k<1024 ? a[bt,k] : x[bt,k-1024] )  (cat(a, x) order)
__global__ void conv_cat_kernel(const float* __restrict__ x,
                                const float* __restrict__ a) {
    size_t i    = (size_t)blockIdx.x * blockDim.x + threadIdx.x;
    size_t base = i * 4;                        // total 33,554,432 halves
    int bt = (int)(base >> 11);
    int k  = (int)(base & 2047);
    const float* src = (k < 1024) ? (a + (size_t)bt * 1024 + k)
                                  : (x + (size_t)bt * 1024 + (k - 1024));
    float4 v = *reinterpret_cast<const float4*>(src);
    __half2* dst = reinterpret_cast<__half2*>(g_A + base);
    dst[0] = __floats2half2_rn(v.x, v.y);
    dst[1] = __floats2half2_rn(v.z, v.w);
}

// g_W stacks [Wf;Wi;Wc;Wo] as fp16
__global__ void conv_w_kernel(const float* __restrict__ Wf,
                              const float* __restrict__ Wi,
                              const float* __restrict__ Wc,
                              const float* __restrict__ Wo) {
    size_t i    = (size_t)blockIdx.x * blockDim.x + threadIdx.x;
    size_t base = i * 4;                        // total 8,388,608 halves
    int n = (int)(base >> 11);
    int k = (int)(base & 2047);
    int g = n >> 10;
    int r = n & 1023;
    const float* W = (g == 0) ? Wf : (g == 1) ? Wi : (g == 2) ? Wc : Wo;
    float4 v = *reinterpret_cast<const float4*>(W + (size_t)r * 2048 + k);
    __half2* dst = reinterpret_cast<__half2*>(g_W + base);
    dst[0] = __floats2half2_rn(v.x, v.y);
    dst[1] = __floats2half2_rn(v.z, v.w);
}

// ---------------- fused GEMM (HMMA) + LSTM gate kernel ----------------
// grid.x = hblk (16, fast -> W stays L2 resident), grid.y = mblk (128)
__global__ void __launch_bounds__(THREADS, 1)
lstm_fused_kernel(const float* __restrict__ c_in,
                  const float* __restrict__ bfp, const float* __restrict__ bip,
                  const float* __restrict__ bcp, const float* __restrict__ bop,
                  float* __restrict__ out) {
    extern __shared__ char smem[];
    const uint32_t sbase = smem_u32(smem);
    const int tid  = threadIdx.x;
    const int wid  = tid >> 5;
    const int lid  = tid & 31;
    const int wm   = wid & 3;        // warp M index (0..3) -> rows wm*32..+32
    const int wn   = wid >> 2;       // warp N index (0..1) -> cols wn*128..+128
    const int hblk = blockIdx.x;     // 0..15
    const int mblk = blockIdx.y;     // 0..127

    // ---- stage loader: A rows m 0..127, B rows n' = h_local*4 + gate ----
    const __half* Ag = g_A + (size_t)(mblk * MT) * KD;
    const __half* Bg = g_W + (size_t)(hblk * 64) * KD;   // + gate*1024*KD per row

    auto load_stage = [&](int kt, int st) {
        const uint32_t abase = sbase + st * STAGE_SZ;
        const uint32_t bbase = abase + A_TILE;
        const char* As = (const char*)(Ag + (size_t)kt * KT);
        const char* Bs = (const char*)(Bg + (size_t)kt * KT);
        #pragma unroll
        for (int id = tid; id < 1024; id += THREADS) {   // A: 128 rows x 8 x 16B
            int r = id >> 3, cc = id & 7;
            cpa16(abase + SW128(r * 128 + cc * 16),
                  As + (size_t)r * (KD * 2) + cc * 16);
        }
        #pragma unroll
        for (int id = tid; id < 2048; id += THREADS) {   // B: 256 rows x 8 x 16B
            int r = id >> 3, cc = id & 7;
            int gate = r & 3;
            int hl   = r >> 2;
            cpa16(bbase + SW128(r * 128 + cc * 16),
                  Bs + ((size_t)gate * 1024 + hl) * (KD * 2) + cc * 16);
        }
        cp_commit();
    };

    load_stage(0, 0);
    load_stage(1, 1);

    float acc[2][16][4];
    #pragma unroll
    for (int mt = 0; mt < 2; ++mt)
        #pragma unroll
        for (int j = 0; j < 16; ++j)
            #pragma unroll
            for (int v = 0; v < 4; ++v) acc[mt][j][v] = 0.0f;

    // precomputed ldmatrix lane addressing (within-row byte offsets, SW128)
    const int a_row = wm * 32 + (lid & 15);              // + mt*16
    const int a_col = (lid >> 4) * 16;                   // + s*32
    const int b_t   = lid >> 3;
    const int b_row = wn * 128 + ((b_t >> 1) << 3) + (lid & 7);  // + j2*16
    const int b_col = (b_t & 1) * 16;                    // + s*32

    // ---- main loop over 32 k-tiles, 3-stage pipeline ----
    for (int kt = 0; kt < NKT; ++kt) {
        cp_wait<STAGES - 2>();
        __syncthreads();
        if (kt + 2 < NKT) load_stage(kt + 2, (kt + 2) % STAGES);

        const uint32_t abase = sbase + (kt % STAGES) * STAGE_SZ;
        const uint32_t bbase = abase + A_TILE;

        #pragma unroll
        for (int s = 0; s < 4; ++s) {                    // 4 k16 steps
            uint32_t af[2][4];
            #pragma unroll
            for (int mt = 0; mt < 2; ++mt)
                ldmx4(af[mt][0], af[mt][1], af[mt][2], af[mt][3],
                      abase + SW128((a_row + mt * 16) * 128 + s * 32 + a_col));

            uint32_t bf[8][4];                           // j2 pairs: {b0,b1,b0',b1'}
            #pragma unroll
            for (int j2 = 0; j2 < 8; ++j2)
                ldmx4(bf[j2][0], bf[j2][1], bf[j2][2], bf[j2][3],
                      bbase + SW128((b_row + j2 * 16) * 128 + s * 32 + b_col));

            #pragma unroll
            for (int mt = 0; mt < 2; ++mt)
                #pragma unroll
                for (int j2 = 0; j2 < 8; ++j2) {
                    mma16816(acc[mt][j2 * 2],     af[mt], &bf[j2][0]);
                    mma16816(acc[mt][j2 * 2 + 1], af[mt], &bf[j2][2]);
                }
        }
    }

    // ---- fused epilogue: two 128x128 chunks (32 h x 4 gates each) ----
    float* buf = reinterpret_cast<float*>(smem);
    const int h    = tid & 31;                 // lane-as-h: coalesced global I/O
    const int mr0  = tid >> 5;                 // 8 m-rows per pass
    const int row0 = mblk * MT;

    #pragma unroll
    for (int ch = 0; ch < 2; ++ch) {
        __syncthreads();                       // prior consumers (or GEMM) done
        if (wn == ch) {
            #pragma unroll
            for (int mt = 0; mt < 2; ++mt)
                #pragma unroll
                for (int j = 0; j < 16; ++j) {
                    const int r = wm * 32 + mt * 16 + (lid >> 2);
                    const int cc = j * 8 + (lid & 3) * 2;
                    buf[r * EPI_PITCH + cc]                    = acc[mt][j][0];
                    buf[r * EPI_PITCH + cc + 1]                = acc[mt][j][1];
                    buf[(r + 8) * EPI_PITCH + cc]              = acc[mt][j][2];
                    buf[(r + 8) * EPI_PITCH + cc + 1]          = acc[mt][j][3];
                }
        }
        __syncthreads();

        const int hg = hblk * 64 + ch * 32 + h;
        const float bF = __ldg(bfp + hg), bI = __ldg(bip + hg);
        const float bC = __ldg(bcp + hg), bO = __ldg(bop + hg);

        #pragma unroll 4
        for (int it = 0; it < 16; ++it) {
            const int m = it * 8 + mr0;
            float4 gv = *reinterpret_cast<float4*>(&buf[m * EPI_PITCH + h * 4]);
            const size_t oidx = (size_t)(row0 + m) * HD + hg;
            float fv = sigf(gv.x + bF);
            float iv = sigf(gv.y + bI);
            float gg = tanhfast(gv.z + bC);
            float ov = sigf(gv.w + bO);
            float cv = fv * __ldg(c_in + oidx) + iv * gg;
            float av = ov * tanhfast(cv);
            out[oidx]               = ov;
            out[SEQ_OUT + oidx]     = av;
            out[2 * SEQ_OUT + oidx] = cv;
        }
    }
}

// ---------------- launch ----------------
extern "C" void kernel_launch(void* const* d_in, const int* in_sizes, int n_in,
                              void* d_out, int out_size) {
    const float* x  = (const float*)d_in[0];
    const float* a  = (const float*)d_in[1];
    const float* c  = (const float*)d_in[2];
    const float* Wf = (const float*)d_in[3];
    const float* bf = (const float*)d_in[4];
    const float* Wi = (const float*)d_in[5];
    const float* bi = (const float*)d_in[6];
    const float* Wc = (const float*)d_in[7];
    const float* bc = (const float*)d_in[8];
    const float* Wo = (const float*)d_in[9];
    const float* bo = (const float*)d_in[10];
    float* out = (float*)d_out;

    conv_cat_kernel<<<32768, 256>>>(x, a);
    conv_w_kernel<<<8192, 256>>>(Wf, Wi, Wc, Wo);

    static int smem_set = 0;
    if (!smem_set) {
        cudaFuncSetAttribute(lstm_fused_kernel,
                             cudaFuncAttributeMaxDynamicSharedMemorySize, SMEM_TOTAL);
        smem_set = 1;
    }
    dim3 grid(16, 128, 1);
    lstm_fused_kernel<<<grid, THREADS, SMEM_TOTAL>>>(c, bf, bi, bc, bo, out);
}

// round 8
// speedup vs baseline: 1.0207x; 1.0207x over previous
#include <cuda_runtime.h>
#include <cuda_fp16.h>
#include <cstdint>
#include <cstddef>

// ---------------- problem dims ----------------
#define BT    16384              // B*T rows
#define HD    1024               // hidden dim
#define KD    2048               // h + x contraction dim
#define NW    4096               // 4 gates * HD weight rows
#define SEQ_OUT (16384 * 1024)   // elements per output tensor

// ---------------- GEMM tiling ----------------
#define MT      128              // CTA M
#define NT      256              // CTA N = 4 gates x 64 h (gate-interleaved)
#define KT      64               // K per SMEM stage (128 B rows, SW128)
#define NKT     (KD / KT)        // 32 k-tiles
#define THREADS 256              // 8 warps: 2 (M) x 4 (N), warp tile 64x64
#define STAGES  3
#define A_TILE  (MT * 128)       // 16 KB
#define B_TILE  (NT * 128)       // 32 KB
#define STAGE_SZ (A_TILE + B_TILE)            // 48 KB
#define SMEM_TOTAL (STAGES * STAGE_SZ)        // 144 KB (epilogue reuses it)
#define EPI_PITCH 132            // floats per row in epilogue buffer

// fp16 scratch (device globals: no runtime allocation)
__device__ __half g_A[(size_t)BT * KD];   // 64 MB  cat(a,x) fp16
__device__ __half g_W[(size_t)NW * KD];   // 16 MB  [Wf;Wi;Wc;Wo] fp16

#define DINL __device__ __forceinline__
#define SW128(o) ((uint32_t)(o) ^ ((((uint32_t)(o)) >> 3) & 0x70u))

// ---------------- PTX helpers (plain sm_80-era: compile for compute_103) ----
DINL uint32_t smem_u32(const void* p) {
    uint32_t a;
    asm("{ .reg .u64 t; cvta.to.shared.u64 t, %1; cvt.u32.u64 %0, t; }"
        : "=r"(a) : "l"(p));
    return a;
}
DINL void cpa16(uint32_t dst, const void* src) {
    asm volatile("cp.async.cg.shared.global [%0], [%1], 16;"
                 :: "r"(dst), "l"(src));
}
DINL void cp_commit() { asm volatile("cp.async.commit_group;" ::: "memory"); }
template<int N> DINL void cp_wait() {
    asm volatile("cp.async.wait_group %0;" :: "n"(N) : "memory");
}
DINL void ldmx4(uint32_t& r0, uint32_t& r1, uint32_t& r2, uint32_t& r3, uint32_t addr) {
    asm volatile("ldmatrix.sync.aligned.m8n8.x4.shared.b16 {%0,%1,%2,%3}, [%4];"
                 : "=r"(r0), "=r"(r1), "=r"(r2), "=r"(r3) : "r"(addr));
}
DINL void mma16816(float* d, const uint32_t* a, const uint32_t* b) {
    asm volatile(
        "mma.sync.aligned.m16n8k16.row.col.f32.f16.f16.f32 "
        "{%0,%1,%2,%3}, {%4,%5,%6,%7}, {%8,%9}, {%0,%1,%2,%3};"
        : "+f"(d[0]), "+f"(d[1]), "+f"(d[2]), "+f"(d[3])
        : "r"(a[0]), "r"(a[1]), "r"(a[2]), "r"(a[3]), "r"(b[0]), "r"(b[1]));
}
DINL float sigf(float v)     { return __fdividef(1.0f, 1.0f + __expf(-v)); }
DINL float tanhfast(float v) { return 1.0f - __fdividef(2.0f, 1.0f + __expf(2.0f * v)); }

// ---------------- conversion kernels ----------------
// g_A[bt, k] = fp16( k<1024 ? a[bt,k] : x[bt,k-1024] )  (cat(a, x) order)
__global__ void conv_cat_kernel(const float* __restrict__ x,
                                const float* __restrict__ a) {
    size_t i    = (size_t)blockIdx.x * blockDim.x + threadIdx.x;
    size_t base = i * 4;                        // total 33,554,432 halves
    int bt = (int)(base >> 11);
    int k  = (int)(base & 2047);
    const float* src = (k < 1024) ? (a + (size_t)bt * 1024 + k)
                                  : (x + (size_t)bt * 1024 + (k - 1024));
    float4 v = *reinterpret_cast<const float4*>(src);
    __half2* dst = reinterpret_cast<__half2*>(g_A + base);
    dst[0] = __floats2half2_rn(v.x, v.y);
    dst[1] = __floats2half2_rn(v.z, v.w);
}

// g_W stacks [Wf;Wi;Wc;Wo] as fp16
__global__ void conv_w_kernel(const float* __restrict__ Wf,
                              const float* __restrict__ Wi,
                              const float* __restrict__ Wc,
                              const float* __restrict__ Wo) {
    size_t i    = (size_t)blockIdx.x * blockDim.x + threadIdx.x;
    size_t base = i * 4;                        // total 8,388,608 halves
    int n = (int)(base >> 11);
    int k = (int)(base & 2047);
    int g = n >> 10;
    int r = n & 1023;
    const float* W = (g == 0) ? Wf : (g == 1) ? Wi : (g == 2) ? Wc : Wo;
    float4 v = *reinterpret_cast<const float4*>(W + (size_t)r * 2048 + k);
    __half2* dst = reinterpret_cast<__half2*>(g_W + base);
    dst[0] = __floats2half2_rn(v.x, v.y);
    dst[1] = __floats2half2_rn(v.z, v.w);
}

// ---------------- fused GEMM (HMMA) + LSTM gate kernel ----------------
// grid.x = hblk (16, fast -> W stays L2 resident), grid.y = mblk (128)
// warp grid: wm = wid&1 (2 x 64 rows), wn = wid>>1 (4 x 64 cols)
__global__ void __launch_bounds__(THREADS, 1)
lstm_fused_kernel(const float* __restrict__ c_in,
                  const float* __restrict__ bfp, const float* __restrict__ bip,
                  const float* __restrict__ bcp, const float* __restrict__ bop,
                  float* __restrict__ out) {
    extern __shared__ char smem[];
    const uint32_t sbase = smem_u32(smem);
    const int tid  = threadIdx.x;
    const int wid  = tid >> 5;
    const int lid  = tid & 31;
    const int wm   = wid & 1;        // warp M index -> rows wm*64..+64
    const int wn   = wid >> 1;       // warp N index -> cols wn*64..+64
    const int hblk = blockIdx.x;     // 0..15
    const int mblk = blockIdx.y;     // 0..127

    // ---- stage loader: A rows m 0..127, B rows n' = h_local*4 + gate ----
    const __half* Ag = g_A + (size_t)(mblk * MT) * KD;
    const __half* Bg = g_W + (size_t)(hblk * 64) * KD;   // + gate*1024*KD per row

    auto load_stage = [&](int kt, int st) {
        const uint32_t abase = sbase + st * STAGE_SZ;
        const uint32_t bbase = abase + A_TILE;
        const char* As = (const char*)(Ag + (size_t)kt * KT);
        const char* Bs = (const char*)(Bg + (size_t)kt * KT);
        #pragma unroll
        for (int id = tid; id < 1024; id += THREADS) {   // A: 128 rows x 8 x 16B
            int r = id >> 3, cc = id & 7;
            cpa16(abase + SW128(r * 128 + cc * 16),
                  As + (size_t)r * (KD * 2) + cc * 16);
        }
        #pragma unroll
        for (int id = tid; id < 2048; id += THREADS) {   // B: 256 rows x 8 x 16B
            int r = id >> 3, cc = id & 7;
            int gate = r & 3;
            int hl   = r >> 2;
            cpa16(bbase + SW128(r * 128 + cc * 16),
                  Bs + ((size_t)gate * 1024 + hl) * (KD * 2) + cc * 16);
        }
        cp_commit();
    };

    load_stage(0, 0);
    load_stage(1, 1);

    // acc[mt 0..3][j 0..7][4] : warp tile 64 (M) x 64 (N)
    float acc[4][8][4];
    #pragma unroll
    for (int mt = 0; mt < 4; ++mt)
        #pragma unroll
        for (int j = 0; j < 8; ++j)
            #pragma unroll
            for (int v = 0; v < 4; ++v) acc[mt][j][v] = 0.0f;

    // ldmatrix lane addressing (byte offsets pre-swizzle)
    const int a_row = wm * 64 + (lid & 15);              // + mt*16
    const int a_col = (lid >> 4) * 16;                   // + s*32
    const int b_t   = lid >> 3;
    const int b_row = wn * 64 + ((b_t >> 1) << 3) + (lid & 7);  // + j2*16
    const int b_col = (b_t & 1) * 16;                    // + s*32

    // ---- main loop over 32 k-tiles, 3-stage pipeline ----
    for (int kt = 0; kt < NKT; ++kt) {
        cp_wait<STAGES - 2>();
        __syncthreads();
        if (kt + 2 < NKT) load_stage(kt + 2, (kt + 2) % STAGES);

        const uint32_t abase = sbase + (kt % STAGES) * STAGE_SZ;
        const uint32_t bbase = abase + A_TILE;

        #pragma unroll
        for (int s = 0; s < 4; ++s) {                    // 4 k16 steps
            uint32_t af[4][4];
            #pragma unroll
            for (int mt = 0; mt < 4; ++mt)
                ldmx4(af[mt][0], af[mt][1], af[mt][2], af[mt][3],
                      abase + SW128((a_row + mt * 16) * 128 + s * 32 + a_col));

            uint32_t bf[4][4];                 // j2: {n0-7 k0-7, n0-7 k8-15, n8-15 k0-7, n8-15 k8-15}
            #pragma unroll
            for (int j2 = 0; j2 < 4; ++j2)
                ldmx4(bf[j2][0], bf[j2][1], bf[j2][2], bf[j2][3],
                      bbase + SW128((b_row + j2 * 16) * 128 + s * 32 + b_col));

            #pragma unroll
            for (int mt = 0; mt < 4; ++mt)
                #pragma unroll
                for (int j2 = 0; j2 < 4; ++j2) {
                    mma16816(acc[mt][j2 * 2],     af[mt], &bf[j2][0]);
                    mma16816(acc[mt][j2 * 2 + 1], af[mt], &bf[j2][2]);
                }
        }
    }

    // ---- fused epilogue: two 128x128 chunks (32 h x 4 gates each) ----
    float* buf = reinterpret_cast<float*>(smem);
    const int h    = tid & 31;                 // lane-as-h: coalesced global I/O
    const int mr0  = tid >> 5;                 // 8 m-rows per pass
    const int row0 = mblk * MT;

    #pragma unroll
    for (int ch = 0; ch < 2; ++ch) {
        __syncthreads();                       // prior consumers (or GEMM) done
        if ((wn >> 1) == ch) {
            const int ccol0 = (wn & 1) * 64;
            #pragma unroll
            for (int mt = 0; mt < 4; ++mt)
                #pragma unroll
                for (int j = 0; j < 8; ++j) {
                    const int r  = wm * 64 + mt * 16 + (lid >> 2);
                    const int cc = ccol0 + j * 8 + (lid & 3) * 2;
                    buf[r * EPI_PITCH + cc]           = acc[mt][j][0];
                    buf[r * EPI_PITCH + cc + 1]       = acc[mt][j][1];
                    buf[(r + 8) * EPI_PITCH + cc]     = acc[mt][j][2];
                    buf[(r + 8) * EPI_PITCH + cc + 1] = acc[mt][j][3];
                }
        }
        __syncthreads();

        const int hg = hblk * 64 + ch * 32 + h;
        const float bF = __ldg(bfp + hg), bI = __ldg(bip + hg);
        const float bC = __ldg(bcp + hg), bO = __ldg(bop + hg);

        #pragma unroll 4
        for (int it = 0; it < 16; ++it) {
            const int m = it * 8 + mr0;
            float4 gv = *reinterpret_cast<float4*>(&buf[m * EPI_PITCH + h * 4]);
            const size_t oidx = (size_t)(row0 + m) * HD + hg;
            float fv = sigf(gv.x + bF);
            float iv = sigf(gv.y + bI);
            float gg = tanhfast(gv.z + bC);
            float ov = sigf(gv.w + bO);
            float cv = fv * __ldg(c_in + oidx) + iv * gg;
            float av = ov * tanhfast(cv);
            out[oidx]               = ov;
            out[SEQ_OUT + oidx]     = av;
            out[2 * SEQ_OUT + oidx] = cv;
        }
    }
}

// ---------------- launch ----------------
extern "C" void kernel_launch(void* const* d_in, const int* in_sizes, int n_in,
                              void* d_out, int out_size) {
    const float* x  = (const float*)d_in[0];
    const float* a  = (const float*)d_in[1];
    const float* c  = (const float*)d_in[2];
    const float* Wf = (const float*)d_in[3];
    const float* bf = (const float*)d_in[4];
    const float* Wi = (const float*)d_in[5];
    const float* bi = (const float*)d_in[6];
    const float* Wc = (const float*)d_in[7];
    const float* bc = (const float*)d_in[8];
    const float* Wo = (const float*)d_in[9];
    const float* bo = (const float*)d_in[10];
    float* out = (float*)d_out;

    conv_cat_kernel<<<32768, 256>>>(x, a);
    conv_w_kernel<<<8192, 256>>>(Wf, Wi, Wc, Wo);

    static int smem_set = 0;
    if (!smem_set) {
        cudaFuncSetAttribute(lstm_fused_kernel,
                             cudaFuncAttributeMaxDynamicSharedMemorySize, SMEM_TOTAL);
        smem_set = 1;
    }
    dim3 grid(16, 128, 1);
    lstm_fused_kernel<<<grid, THREADS, SMEM_TOTAL>>>(c, bf, bi, bc, bo, out);
}

// round 9
// speedup vs baseline: 1.0400x; 1.0189x over previous
#include <cuda_runtime.h>
#include <cuda_fp16.h>
#include <cstdint>
#include <cstddef>

// ---------------- problem dims ----------------
#define BT    16384              // B*T rows
#define HD    1024              // hidden dim
#define KD    2048              // h + x contraction dim
#define NW    4096              // 4 gates * HD weight rows
#define SEQ_OUT (16384 * 1024)  // elements per output tensor

// ---------------- GEMM tiling ----------------
#define MT      128              // CTA M
#define NT      256              // CTA N = 4 gates x 64 h (gate-interleaved)
#define KT      64               // K per SMEM stage (128 B rows, SW128)
#define NKT     (KD / KT)        // 32 k-tiles
#define THREADS 512              // 16 warps: 2 (M) x 8 (N), warp tile 64x32
#define STAGES  3
#define A_TILE  (MT * 128)       // 16 KB
#define B_TILE  (NT * 128)       // 32 KB
#define STAGE_SZ (A_TILE + B_TILE)            // 48 KB
#define SMEM_TOTAL (STAGES * STAGE_SZ)        // 144 KB (epilogue reuses it)
#define EPI_PITCH 132            // floats per row in epilogue buffer

// fp16 scratch (device globals: no runtime allocation)
__device__ __half g_A[(size_t)BT * KD];   // 64 MB  cat(a,x) fp16
__device__ __half g_W[(size_t)NW * KD];   // 16 MB  [Wf;Wi;Wc;Wo] fp16

#define DINL __device__ __forceinline__
#define SW128(o) ((uint32_t)(o) ^ ((((uint32_t)(o)) >> 3) & 0x70u))

// ---------------- PTX helpers (plain sm_80-era: compile for compute_103) ----
DINL uint32_t smem_u32(const void* p) {
    uint32_t a;
    asm("{ .reg .u64 t; cvta.to.shared.u64 t, %1; cvt.u32.u64 %0, t; }"
        : "=r"(a) : "l"(p));
    return a;
}
DINL void cpa16(uint32_t dst, const void* src) {
    asm volatile("cp.async.cg.shared.global [%0], [%1], 16;"
                 :: "r"(dst), "l"(src));
}
DINL void cp_commit() { asm volatile("cp.async.commit_group;" ::: "memory"); }
template<int N> DINL void cp_wait() {
    asm volatile("cp.async.wait_group %0;" :: "n"(N) : "memory");
}
DINL void ldmx4(uint32_t& r0, uint32_t& r1, uint32_t& r2, uint32_t& r3, uint32_t addr) {
    asm volatile("ldmatrix.sync.aligned.m8n8.x4.shared.b16 {%0,%1,%2,%3}, [%4];"
                 : "=r"(r0), "=r"(r1), "=r"(r2), "=r"(r3) : "r"(addr));
}
DINL void mma16816(float* d, const uint32_t* a, const uint32_t* b) {
    asm volatile(
        "mma.sync.aligned.m16n8k16.row.col.f32.f16.f16.f32 "
        "{%0,%1,%2,%3}, {%4,%5,%6,%7}, {%8,%9}, {%0,%1,%2,%3};"
        : "+f"(d[0]), "+f"(d[1]), "+f"(d[2]), "+f"(d[3])
        : "r"(a[0]), "r"(a[1]), "r"(a[2]), "r"(a[3]), "r"(b[0]), "r"(b[1]));
}
DINL float sigf(float v)     { return __fdividef(1.0f, 1.0f + __expf(-v)); }
DINL float tanhfast(float v) { return 1.0f - __fdividef(2.0f, 1.0f + __expf(2.0f * v)); }

// ---------------- conversion kernels ----------------
// g_A[bt, k] = fp16( k<1024 ? a[bt,k] : x[bt,k-1024] )  (cat(a, x) order)
__global__ void conv_cat_kernel(const float* __restrict__ x,
                                const float* __restrict__ a) {
    size_t i    = (size_t)blockIdx.x * blockDim.x + threadIdx.x;
    size_t base = i * 4;                        // total 33,554,432 halves
    int bt = (int)(base >> 11);
    int k  = (int)(base & 2047);
    const float* src = (k < 1024) ? (a + (size_t)bt * 1024 + k)
                                  : (x + (size_t)bt * 1024 + (k - 1024));
    float4 v = *reinterpret_cast<const float4*>(src);
    __half2* dst = reinterpret_cast<__half2*>(g_A + base);
    dst[0] = __floats2half2_rn(v.x, v.y);
    dst[1] = __floats2half2_rn(v.z, v.w);
}

// g_W stacks [Wf;Wi;Wc;Wo] as fp16
__global__ void conv_w_kernel(const float* __restrict__ Wf,
                              const float* __restrict__ Wi,
                              const float* __restrict__ Wc,
                              const float* __restrict__ Wo) {
    size_t i    = (size_t)blockIdx.x * blockDim.x + threadIdx.x;
    size_t base = i * 4;                        // total 8,388,608 halves
    int n = (int)(base >> 11);
    int k = (int)(base & 2047);
    int g = n >> 10;
    int r = n & 1023;
    const float* W = (g == 0) ? Wf : (g == 1) ? Wi : (g == 2) ? Wc : Wo;
    float4 v = *reinterpret_cast<const float4*>(W + (size_t)r * 2048 + k);
    __half2* dst = reinterpret_cast<__half2*>(g_W + base);
    dst[0] = __floats2half2_rn(v.x, v.y);
    dst[1] = __floats2half2_rn(v.z, v.w);
}

// ---------------- fused GEMM (HMMA) + LSTM gate kernel ----------------
// grid.x = hblk (16, fast -> W stays L2 resident), grid.y = mblk (128)
// warp grid: wm = wid&1 (2 x 64 rows), wn = wid>>1 (8 x 32 cols)
__global__ void __launch_bounds__(THREADS, 1)
lstm_fused_kernel(const float* __restrict__ c_in,
                  const float* __restrict__ bfp, const float* __restrict__ bip,
                  const float* __restrict__ bcp, const float* __restrict__ bop,
                  float* __restrict__ out) {
    extern __shared__ char smem[];
    const uint32_t sbase = smem_u32(smem);
    const int tid  = threadIdx.x;
    const int wid  = tid >> 5;
    const int lid  = tid & 31;
    const int wm   = wid & 1;        // warp M index -> rows wm*64..+64
    const int wn   = wid >> 1;       // warp N index -> cols wn*32..+32
    const int hblk = blockIdx.x;     // 0..15
    const int mblk = blockIdx.y;     // 0..127

    // ---- stage loader: A rows m 0..127, B rows n' = h_local*4 + gate ----
    const __half* Ag = g_A + (size_t)(mblk * MT) * KD;
    const __half* Bg = g_W + (size_t)(hblk * 64) * KD;   // + gate*1024*KD per row

    auto load_stage = [&](int kt, int st) {
        const uint32_t abase = sbase + st * STAGE_SZ;
        const uint32_t bbase = abase + A_TILE;
        const char* As = (const char*)(Ag + (size_t)kt * KT);
        const char* Bs = (const char*)(Bg + (size_t)kt * KT);
        #pragma unroll
        for (int id = tid; id < 1024; id += THREADS) {   // A: 128 rows x 8 x 16B
            int r = id >> 3, cc = id & 7;
            cpa16(abase + SW128(r * 128 + cc * 16),
                  As + (size_t)r * (KD * 2) + cc * 16);
        }
        #pragma unroll
        for (int id = tid; id < 2048; id += THREADS) {   // B: 256 rows x 8 x 16B
            int r = id >> 3, cc = id & 7;
            int gate = r & 3;
            int hl   = r >> 2;
            cpa16(bbase + SW128(r * 128 + cc * 16),
                  Bs + ((size_t)gate * 1024 + hl) * (KD * 2) + cc * 16);
        }
        cp_commit();
    };

    load_stage(0, 0);
    load_stage(1, 1);

    // acc[mt 0..3][j 0..3][4] : warp tile 64 (M) x 32 (N)
    float acc[4][4][4];
    #pragma unroll
    for (int mt = 0; mt < 4; ++mt)
        #pragma unroll
        for (int j = 0; j < 4; ++j)
            #pragma unroll
            for (int v = 0; v < 4; ++v) acc[mt][j][v] = 0.0f;

    // ldmatrix lane addressing (byte offsets pre-swizzle)
    const int a_row = wm * 64 + (lid & 15);              // + mt*16
    const int a_col = (lid >> 4) * 16;                   // + s*32
    const int b_t   = lid >> 3;
    const int b_row = wn * 32 + ((b_t >> 1) << 3) + (lid & 7);  // + j2*16
    const int b_col = (b_t & 1) * 16;                    // + s*32

    // ---- main loop over 32 k-tiles, 3-stage pipeline ----
    for (int kt = 0; kt < NKT; ++kt) {
        cp_wait<STAGES - 2>();
        __syncthreads();
        if (kt + 2 < NKT) load_stage(kt + 2, (kt + 2) % STAGES);

        const uint32_t abase = sbase + (kt % STAGES) * STAGE_SZ;
        const uint32_t bbase = abase + A_TILE;

        #pragma unroll
        for (int s = 0; s < 4; ++s) {                    // 4 k16 steps
            uint32_t af[4][4];
            #pragma unroll
            for (int mt = 0; mt < 4; ++mt)
                ldmx4(af[mt][0], af[mt][1], af[mt][2], af[mt][3],
                      abase + SW128((a_row + mt * 16) * 128 + s * 32 + a_col));

            uint32_t bf[2][4];       // j2: {n0-7 k0-7, n0-7 k8-15, n8-15 ...}
            #pragma unroll
            for (int j2 = 0; j2 < 2; ++j2)
                ldmx4(bf[j2][0], bf[j2][1], bf[j2][2], bf[j2][3],
                      bbase + SW128((b_row + j2 * 16) * 128 + s * 32 + b_col));

            #pragma unroll
            for (int mt = 0; mt < 4; ++mt)
                #pragma unroll
                for (int j2 = 0; j2 < 2; ++j2) {
                    mma16816(acc[mt][j2 * 2],     af[mt], &bf[j2][0]);
                    mma16816(acc[mt][j2 * 2 + 1], af[mt], &bf[j2][2]);
                }
        }
    }

    // ---- fused epilogue: two 128x128 chunks (32 h x 4 gates each) ----
    float* buf = reinterpret_cast<float*>(smem);
    const int h    = tid & 31;                 // lane-as-h: coalesced global I/O
    const int mr0  = tid >> 5;                 // 16 m-rows per pass
    const int row0 = mblk * MT;

    #pragma unroll
    for (int ch = 0; ch < 2; ++ch) {
        __syncthreads();                       // prior consumers (or GEMM) done
        if ((wn >> 2) == ch) {
            const int ccol0 = (wn & 3) * 32;
            #pragma unroll
            for (int mt = 0; mt < 4; ++mt)
                #pragma unroll
                for (int j = 0; j < 4; ++j) {
                    const int r  = wm * 64 + mt * 16 + (lid >> 2);
                    const int cc = ccol0 + j * 8 + (lid & 3) * 2;
                    buf[r * EPI_PITCH + cc]           = acc[mt][j][0];
                    buf[r * EPI_PITCH + cc + 1]       = acc[mt][j][1];
                    buf[(r + 8) * EPI_PITCH + cc]     = acc[mt][j][2];
                    buf[(r + 8) * EPI_PITCH + cc + 1] = acc[mt][j][3];
                }
        }
        __syncthreads();

        const int hg = hblk * 64 + ch * 32 + h;
        const float bF = __ldg(bfp + hg), bI = __ldg(bip + hg);
        const float bC = __ldg(bcp + hg), bO = __ldg(bop + hg);

        #pragma unroll 4
        for (int it = 0; it < 8; ++it) {
            const int m = it * 16 + mr0;
            float4 gv = *reinterpret_cast<float4*>(&buf[m * EPI_PITCH + h * 4]);
            const size_t oidx = (size_t)(row0 + m) * HD + hg;
            float fv = sigf(gv.x + bF);
            float iv = sigf(gv.y + bI);
            float gg = tanhfast(gv.z + bC);
            float ov = sigf(gv.w + bO);
            float cv = fv * __ldg(c_in + oidx) + iv * gg;
            float av = ov * tanhfast(cv);
            out[oidx]               = ov;
            out[SEQ_OUT + oidx]     = av;
            out[2 * SEQ_OUT + oidx] = cv;
        }
    }
}

// ---------------- launch ----------------
extern "C" void kernel_launch(void* const* d_in, const int* in_sizes, int n_in,
                              void* d_out, int out_size) {
    const float* x  = (const float*)d_in[0];
    const float* a  = (const float*)d_in[1];
    const float* c  = (const float*)d_in[2];
    const float* Wf = (const float*)d_in[3];
    const float* bf = (const float*)d_in[4];
    const float* Wi = (const float*)d_in[5];
    const float* bi = (const float*)d_in[6];
    const float* Wc = (const float*)d_in[7];
    const float* bc = (const float*)d_in[8];
    const float* Wo = (const float*)d_in[9];
    const float* bo = (const float*)d_in[10];
    float* out = (float*)d_out;

    conv_cat_kernel<<<32768, 256>>>(x, a);
    conv_w_kernel<<<8192, 256>>>(Wf, Wi, Wc, Wo);

    static int smem_set = 0;
    if (!smem_set) {
        cudaFuncSetAttribute(lstm_fused_kernel,
                             cudaFuncAttributeMaxDynamicSharedMemorySize, SMEM_TOTAL);
        smem_set = 1;
    }
    dim3 grid(16, 128, 1);
    lstm_fused_kernel<<<grid, THREADS, SMEM_TOTAL>>>(c, bf, bi, bc, bo, out);
}

// round 10
// speedup vs baseline: 1.2204x; 1.1735x over previous
#include <cuda_runtime.h>
#include <cuda_fp16.h>
#include <cstdint>
#include <cstddef>

// ---------------- problem dims ----------------
#define BT    16384              // B*T rows
#define HD    1024              // hidden dim
#define KD    2048              // h + x contraction dim
#define NW    4096              // 4 gates * HD weight rows
#define SEQ_OUT (16384 * 1024)  // elements per output tensor

// ---------------- GEMM tiling ----------------
#define MT      128              // CTA M
#define NT      128              // CTA N = 4 gates x 32 h (gate-interleaved)
#define KT      64               // K per SMEM stage (128 B rows, SW128)
#define NKT     (KD / KT)        // 32 k-tiles
#define THREADS 256              // 8 warps: 2 (M) x 4 (N), warp tile 64x32
#define STAGES  3
#define A_TILE  (MT * 128)       // 16 KB
#define B_TILE  (NT * 128)       // 16 KB
#define STAGE_SZ (A_TILE + B_TILE)            // 32 KB
#define SMEM_TOTAL (STAGES * STAGE_SZ)        // 96 KB -> 2 CTAs/SM (192 KB)
#define EPI_PITCH 132            // floats per row in epilogue buffer (67.5 KB)

// fp16 scratch (device globals: no runtime allocation)
__device__ __half g_A[(size_t)BT * KD];   // 64 MB  cat(a,x) fp16
__device__ __half g_W[(size_t)NW * KD];   // 16 MB  [Wf;Wi;Wc;Wo] fp16

#define DINL __device__ __forceinline__
#define SW128(o) ((uint32_t)(o) ^ ((((uint32_t)(o)) >> 3) & 0x70u))

// ---------------- PTX helpers (plain sm_80-era: compile for compute_103) ----
DINL uint32_t smem_u32(const void* p) {
    uint32_t a;
    asm("{ .reg .u64 t; cvta.to.shared.u64 t, %1; cvt.u32.u64 %0, t; }"
        : "=r"(a) : "l"(p));
    return a;
}
DINL void cpa16(uint32_t dst, const void* src) {
    asm volatile("cp.async.cg.shared.global [%0], [%1], 16;"
                 :: "r"(dst), "l"(src));
}
DINL void cp_commit() { asm volatile("cp.async.commit_group;" ::: "memory"); }
template<int N> DINL void cp_wait() {
    asm volatile("cp.async.wait_group %0;" :: "n"(N) : "memory");
}
DINL void ldmx4(uint32_t& r0, uint32_t& r1, uint32_t& r2, uint32_t& r3, uint32_t addr) {
    asm volatile("ldmatrix.sync.aligned.m8n8.x4.shared.b16 {%0,%1,%2,%3}, [%4];"
                 : "=r"(r0), "=r"(r1), "=r"(r2), "=r"(r3) : "r"(addr));
}
DINL void mma16816(float* d, const uint32_t* a, const uint32_t* b) {
    asm volatile(
        "mma.sync.aligned.m16n8k16.row.col.f32.f16.f16.f32 "
        "{%0,%1,%2,%3}, {%4,%5,%6,%7}, {%8,%9}, {%0,%1,%2,%3};"
        : "+f"(d[0]), "+f"(d[1]), "+f"(d[2]), "+f"(d[3])
        : "r"(a[0]), "r"(a[1]), "r"(a[2]), "r"(a[3]), "r"(b[0]), "r"(b[1]));
}
DINL float sigf(float v)     { return __fdividef(1.0f, 1.0f + __expf(-v)); }
DINL float tanhfast(float v) { return 1.0f - __fdividef(2.0f, 1.0f + __expf(2.0f * v)); }

// ---------------- conversion kernels ----------------
// g_A[bt, k] = fp16( k<1024 ? a[bt,k] : x[bt,k-1024] )  (cat(a, x) order)
__global__ void conv_cat_kernel(const float* __restrict__ x,
                                const float* __restrict__ a) {
    size_t i    = (size_t)blockIdx.x * blockDim.x + threadIdx.x;
    size_t base = i * 4;                        // total 33,554,432 halves
    int bt = (int)(base >> 11);
    int k  = (int)(base & 2047);
    const float* src = (k < 1024) ? (a + (size_t)bt * 1024 + k)
                                  : (x + (size_t)bt * 1024 + (k - 1024));
    float4 v = *reinterpret_cast<const float4*>(src);
    __half2* dst = reinterpret_cast<__half2*>(g_A + base);
    dst[0] = __floats2half2_rn(v.x, v.y);
    dst[1] = __floats2half2_rn(v.z, v.w);
}

// g_W stacks [Wf;Wi;Wc;Wo] as fp16
__global__ void conv_w_kernel(const float* __restrict__ Wf,
                              const float* __restrict__ Wi,
                              const float* __restrict__ Wc,
                              const float* __restrict__ Wo) {
    size_t i    = (size_t)blockIdx.x * blockDim.x + threadIdx.x;
    size_t base = i * 4;                        // total 8,388,608 halves
    int n = (int)(base >> 11);
    int k = (int)(base & 2047);
    int g = n >> 10;
    int r = n & 1023;
    const float* W = (g == 0) ? Wf : (g == 1) ? Wi : (g == 2) ? Wc : Wo;
    float4 v = *reinterpret_cast<const float4*>(W + (size_t)r * 2048 + k);
    __half2* dst = reinterpret_cast<__half2*>(g_W + base);
    dst[0] = __floats2half2_rn(v.x, v.y);
    dst[1] = __floats2half2_rn(v.z, v.w);
}

// ---------------- fused GEMM (HMMA) + LSTM gate kernel ----------------
// grid.x = nblk (32, fast -> A slice shared in L2), grid.y = mblk (128)
// warp grid: wm = wid&1 (2 x 64 rows), wn = wid>>1 (4 x 32 cols)
__global__ void __launch_bounds__(THREADS, 2)
lstm_fused_kernel(const float* __restrict__ c_in,
                  const float* __restrict__ bfp, const float* __restrict__ bip,
                  const float* __restrict__ bcp, const float* __restrict__ bop,
                  float* __restrict__ out) {
    extern __shared__ char smem[];
    const uint32_t sbase = smem_u32(smem);
    const int tid  = threadIdx.x;
    const int wid  = tid >> 5;
    const int lid  = tid & 31;
    const int wm   = wid & 1;        // warp M index -> rows wm*64..+64
    const int wn   = wid >> 1;       // warp N index -> cols wn*32..+32
    const int nblk = blockIdx.x;     // 0..31  (32 h per block)
    const int mblk = blockIdx.y;     // 0..127

    // ---- stage loader: A rows m 0..127, B rows n' = h_local*4 + gate ----
    const __half* Ag = g_A + (size_t)(mblk * MT) * KD;
    const __half* Bg = g_W + (size_t)(nblk * 32) * KD;   // + gate*1024*KD per row

    auto load_stage = [&](int kt, int st) {
        const uint32_t abase = sbase + st * STAGE_SZ;
        const uint32_t bbase = abase + A_TILE;
        const char* As = (const char*)(Ag + (size_t)kt * KT);
        const char* Bs = (const char*)(Bg + (size_t)kt * KT);
        #pragma unroll
        for (int id = tid; id < 1024; id += THREADS) {   // A: 128 rows x 8 x 16B
            int r = id >> 3, cc = id & 7;
            cpa16(abase + SW128(r * 128 + cc * 16),
                  As + (size_t)r * (KD * 2) + cc * 16);
        }
        #pragma unroll
        for (int id = tid; id < 1024; id += THREADS) {   // B: 128 rows x 8 x 16B
            int r = id >> 3, cc = id & 7;
            int gate = r & 3;
            int hl   = r >> 2;
            cpa16(bbase + SW128(r * 128 + cc * 16),
                  Bs + ((size_t)gate * 1024 + hl) * (KD * 2) + cc * 16);
        }
        cp_commit();
    };

    load_stage(0, 0);
    load_stage(1, 1);

    // acc[mt 0..3][j 0..3][4] : warp tile 64 (M) x 32 (N)
    float acc[4][4][4];
    #pragma unroll
    for (int mt = 0; mt < 4; ++mt)
        #pragma unroll
        for (int j = 0; j < 4; ++j)
            #pragma unroll
            for (int v = 0; v < 4; ++v) acc[mt][j][v] = 0.0f;

    // ldmatrix lane addressing (byte offsets pre-swizzle)
    const int a_row = wm * 64 + (lid & 15);              // + mt*16
    const int a_col = (lid >> 4) * 16;                   // + s*32
    const int b_t   = lid >> 3;
    const int b_row = wn * 32 + ((b_t >> 1) << 3) + (lid & 7);  // + j2*16
    const int b_col = (b_t & 1) * 16;                    // + s*32

    // ---- main loop over 32 k-tiles, 3-stage pipeline ----
    for (int kt = 0; kt < NKT; ++kt) {
        if (kt == NKT - 1) cp_wait<0>(); else cp_wait<1>();
        __syncthreads();
        if (kt + 2 < NKT) load_stage(kt + 2, (kt + 2) % STAGES);

        const uint32_t abase = sbase + (kt % STAGES) * STAGE_SZ;
        const uint32_t bbase = abase + A_TILE;

        #pragma unroll
        for (int s = 0; s < 4; ++s) {                    // 4 k16 steps
            uint32_t af[4][4];
            #pragma unroll
            for (int mt = 0; mt < 4; ++mt)
                ldmx4(af[mt][0], af[mt][1], af[mt][2], af[mt][3],
                      abase + SW128((a_row + mt * 16) * 128 + s * 32 + a_col));

            uint32_t bf[2][4];
            #pragma unroll
            for (int j2 = 0; j2 < 2; ++j2)
                ldmx4(bf[j2][0], bf[j2][1], bf[j2][2], bf[j2][3],
                      bbase + SW128((b_row + j2 * 16) * 128 + s * 32 + b_col));

            #pragma unroll
            for (int mt = 0; mt < 4; ++mt)
                #pragma unroll
                for (int j2 = 0; j2 < 2; ++j2) {
                    mma16816(acc[mt][j2 * 2],     af[mt], &bf[j2][0]);
                    mma16816(acc[mt][j2 * 2 + 1], af[mt], &bf[j2][2]);
                }
        }
    }

    // ---- fused epilogue: one 128x128 chunk (32 h x 4 gates) ----
    float* buf = reinterpret_cast<float*>(smem);
    const int h    = tid & 31;                 // lane-as-h: coalesced global I/O
    const int mr0  = tid >> 5;                 // 8-row stride
    const int row0 = mblk * MT;

    __syncthreads();                           // all reads of stage SMEM done
    {
        const int ccol0 = wn * 32;
        #pragma unroll
        for (int mt = 0; mt < 4; ++mt)
            #pragma unroll
            for (int j = 0; j < 4; ++j) {
                const int r  = wm * 64 + mt * 16 + (lid >> 2);
                const int cc = ccol0 + j * 8 + (lid & 3) * 2;
                buf[r * EPI_PITCH + cc]           = acc[mt][j][0];
                buf[r * EPI_PITCH + cc + 1]       = acc[mt][j][1];
                buf[(r + 8) * EPI_PITCH + cc]     = acc[mt][j][2];
                buf[(r + 8) * EPI_PITCH + cc + 1] = acc[mt][j][3];
            }
    }
    __syncthreads();

    const int hg = nblk * 32 + h;
    const float bF = __ldg(bfp + hg), bI = __ldg(bip + hg);
    const float bC = __ldg(bcp + hg), bO = __ldg(bop + hg);

    #pragma unroll 4
    for (int it = 0; it < 16; ++it) {
        const int m = it * 8 + mr0;
        float4 gv = *reinterpret_cast<float4*>(&buf[m * EPI_PITCH + h * 4]);
        const size_t oidx = (size_t)(row0 + m) * HD + hg;
        float fv = sigf(gv.x + bF);
        float iv = sigf(gv.y + bI);
        float gg = tanhfast(gv.z + bC);
        float ov = sigf(gv.w + bO);
        float cv = fv * __ldg(c_in + oidx) + iv * gg;
        float av = ov * tanhfast(cv);
        out[oidx]               = ov;
        out[SEQ_OUT + oidx]     = av;
        out[2 * SEQ_OUT + oidx] = cv;
    }
}

// ---------------- launch ----------------
extern "C" void kernel_launch(void* const* d_in, const int* in_sizes, int n_in,
                              void* d_out, int out_size) {
    const float* x  = (const float*)d_in[0];
    const float* a  = (const float*)d_in[1];
    const float* c  = (const float*)d_in[2];
    const float* Wf = (const float*)d_in[3];
    const float* bf = (const float*)d_in[4];
    const float* Wi = (const float*)d_in[5];
    const float* bi = (const float*)d_in[6];
    const float* Wc = (const float*)d_in[7];
    const float* bc = (const float*)d_in[8];
    const float* Wo = (const float*)d_in[9];
    const float* bo = (const float*)d_in[10];
    float* out = (float*)d_out;

    conv_cat_kernel<<<32768, 256>>>(x, a);
    conv_w_kernel<<<8192, 256>>>(Wf, Wi, Wc, Wo);

    static int smem_set = 0;
    if (!smem_set) {
        cudaFuncSetAttribute(lstm_fused_kernel,
                             cudaFuncAttributeMaxDynamicSharedMemorySize, SMEM_TOTAL);
        smem_set = 1;
    }
    dim3 grid(32, 128, 1);                     // nblk fast -> A slice L2-shared
    lstm_fused_kernel<<<grid, THREADS, SMEM_TOTAL>>>(c, bf, bi, bc, bo, out);
}